// round 3
// baseline (speedup 1.0000x reference)
#include <cuda_runtime.h>

// Kwta: per-sample exact k-th-largest threshold + mask + NCHW-flat "reshape" permutation.
// x: [32, 56, 56, 256] f32.  dim = 802816, k = ceil(0.2*dim) = 160564.
// out[b][j] = mask(x_flat_nchw[b][j]) where j is reinterpreted in NHWC storage order,
// i.e. out[b*dim + c*3136 + hw] = thresholded x[b*dim + hw*256 + c]  (a 3136x256 transpose).

#define BATCH 32
#define HW    3136      // 56*56
#define CH    256
#define DIM   802816    // HW*CH
#define KSEL  160564u   // ceil(0.2 * DIM)
#define NB    2048

__device__ unsigned int g_hist[3][BATCH][NB];
__device__ unsigned int g_prefix[BATCH];
__device__ unsigned int g_krem[BATCH];
__device__ float        g_thresh[BATCH];

// Order-preserving bijection f32 bits -> u32 (ascending).
__device__ __forceinline__ unsigned int fkey(float f) {
    unsigned int u = __float_as_uint(f);
    return (u & 0x80000000u) ? ~u : (u ^ 0x80000000u);
}

__global__ void zero_kernel() {
    int i = blockIdx.x * blockDim.x + threadIdx.x;
    int total = 3 * BATCH * NB;
    if (i < total) (&g_hist[0][0][0])[i] = 0u;
}

template <int PASS>
__global__ void hist_kernel(const float* __restrict__ x) {
    __shared__ unsigned int sh[NB];
    const int b = blockIdx.y;
    for (int j = threadIdx.x; j < NB; j += blockDim.x) sh[j] = 0u;
    __syncthreads();

    const unsigned int pref = (PASS == 0) ? 0u : g_prefix[b];
    const float4* __restrict__ p4 =
        reinterpret_cast<const float4*>(x + (size_t)b * DIM);
    const int n4 = DIM / 4;
    const int stride = gridDim.x * blockDim.x;

    for (int i = blockIdx.x * blockDim.x + threadIdx.x; i < n4; i += stride) {
        float4 v = p4[i];
        float vals[4] = {v.x, v.y, v.z, v.w};
#pragma unroll
        for (int j = 0; j < 4; j++) {
            unsigned int key = fkey(vals[j]);
            if (PASS == 0) {
                atomicAdd(&sh[key >> 21], 1u);
            } else if (PASS == 1) {
                if ((key >> 21) == (pref >> 21))
                    atomicAdd(&sh[(key >> 10) & 0x7FFu], 1u);
            } else {
                if ((key >> 10) == (pref >> 10))
                    atomicAdd(&sh[key & 0x3FFu], 1u);
            }
        }
    }
    __syncthreads();
    for (int j = threadIdx.x; j < NB; j += blockDim.x) {
        unsigned int c = sh[j];
        if (c) atomicAdd(&g_hist[PASS][b][j], c);
    }
}

// One thread per sample: walk bins from the top, find the bin holding the
// k-th largest, narrow prefix and residual k. Pass 2 emits the float threshold.
__global__ void scan_kernel(int pass) {
    int b = threadIdx.x;
    if (b >= BATCH) return;
    unsigned int k    = (pass == 0) ? KSEL : g_krem[b];
    unsigned int pref = (pass == 0) ? 0u : g_prefix[b];
    const unsigned int* h = g_hist[pass][b];
    const int nb = (pass == 2) ? 1024 : 2048;

    unsigned int cum = 0;
    int sel = 0;
    for (int bin = nb - 1; bin >= 0; --bin) {
        unsigned int c = h[bin];
        cum += c;
        if (cum >= k) { sel = bin; k = k - (cum - c); break; }
    }
    if (pass == 0)      pref = ((unsigned int)sel) << 21;
    else if (pass == 1) pref |= ((unsigned int)sel) << 10;
    else                pref |= (unsigned int)sel;
    g_prefix[b] = pref;
    g_krem[b]   = k;
    if (pass == 2) {
        unsigned int u = (pref & 0x80000000u) ? (pref ^ 0x80000000u) : ~pref;
        g_thresh[b] = __uint_as_float(u);
    }
}

// Fused threshold + 3136x256 -> 256x3136 transpose, 32x32 shared tiles.
__global__ void mask_transpose_kernel(const float* __restrict__ x,
                                      float* __restrict__ out) {
    __shared__ float tile[32][33];
    const int b   = blockIdx.z;
    const float t = g_thresh[b];
    const int c0  = blockIdx.x * 32;   // channel tile
    const int hw0 = blockIdx.y * 32;   // spatial tile
    const float* __restrict__ in = x + (size_t)b * DIM;
    float* __restrict__ o        = out + (size_t)b * DIM;

#pragma unroll
    for (int j = 0; j < 32; j += 8) {
        tile[threadIdx.y + j][threadIdx.x] =
            in[(size_t)(hw0 + threadIdx.y + j) * CH + c0 + threadIdx.x];
    }
    __syncthreads();
#pragma unroll
    for (int j = 0; j < 32; j += 8) {
        float v = tile[threadIdx.x][threadIdx.y + j];
        o[(size_t)(c0 + threadIdx.y + j) * HW + hw0 + threadIdx.x] =
            (v < t) ? 0.0f : v;
    }
}

extern "C" void kernel_launch(void* const* d_in, const int* in_sizes, int n_in,
                              void* d_out, int out_size) {
    const float* x = (const float*)d_in[0];
    float* out = (float*)d_out;

    zero_kernel<<<(3 * BATCH * NB + 255) / 256, 256>>>();

    dim3 hg(32, BATCH);
    hist_kernel<0><<<hg, 256>>>(x);
    scan_kernel<<<1, 32>>>(0);
    hist_kernel<1><<<hg, 256>>>(x);
    scan_kernel<<<1, 32>>>(1);
    hist_kernel<2><<<hg, 256>>>(x);
    scan_kernel<<<1, 32>>>(2);

    mask_transpose_kernel<<<dim3(CH / 32, HW / 32, BATCH), dim3(32, 8)>>>(x, out);
}